// round 6
// baseline (speedup 1.0000x reference)
#include <cuda_runtime.h>
#include <math.h>
#include <stdint.h>

#define NN     8192
#define NB     8192
#define RANGEF 74000.0f
#define INV_W  ((float)NB / RANGEF)
#define GRID   128
#define TPB    1024
#define EB     64          // edge-accumulating blocks (each owns a 32KB smem partial)

// Scratch (__device__ globals; zero-initialized at load; all state is
// self-restoring so every graph replay sees the same initial state).
__device__ float g_part[EB * NN];  // per-edge-block partial sums (fully overwritten)
__device__ float g_S[NN];          // S per node (original order)
__device__ float g_V[NN];          // bucket-grouped copy of S
__device__ int   g_H[NB];          // histogram (starts 0, reset in build)
__device__ int   g_P[NB + 1];      // exclusive prefix of bucket histogram
__device__ float g_C;              // dot(x, p)

// Software grid barrier state (3 slots, self-resetting via departure count)
__device__ int          g_cnt[3];
__device__ int          g_dep[3];
__device__ volatile int g_rel[3];

__device__ __forceinline__ void gbar(int b) {
    __syncthreads();
    if (threadIdx.x == 0) {
        __threadfence();
        if (atomicAdd(&g_cnt[b], 1) == GRID - 1) {
            g_rel[b] = 1;
            __threadfence();
        } else {
            while (g_rel[b] == 0) __nanosleep(64);
        }
        __threadfence();
        if (atomicAdd(&g_dep[b], 1) == GRID - 1) {
            g_cnt[b] = 0;
            g_dep[b] = 0;
            __threadfence();
            g_rel[b] = 0;
        }
    }
    __syncthreads();
}

// Monotone bucket map. MUST be identical at insert and query.
__device__ __forceinline__ int bucket_of(float v, float C) {
    float u = (v - C) * INV_W;
    int b = (int)u;
    if (b < 0) b = 0;
    if (b > NB - 1) b = NB - 1;
    return b;
}

// ---------------------------------------------------------------------------
__global__ void __launch_bounds__(TPB, 1)
fused(const int* __restrict__ ei, const float* __restrict__ p,
      const float* __restrict__ x, float* __restrict__ out,
      int E, int n, float logn) {

    // One 32KB smem buffer, aliased per phase:
    //   edge blocks: float A[8192]   | dot block: double dsh[1024]
    //   build block: int  cnt[8192]
    __shared__ int sbuf[NB];
    __shared__ int wsum[32];
    float*  sA  = (float*)sbuf;
    double* dsh = (double*)sbuf;

    const int t = threadIdx.x;
    const int b = blockIdx.x;

    // ---------------- Phase 1: edges (blocks 0..EB-1) + dot (block EB) ----
    if (b < EB) {
        // zero smem partial
#pragma unroll
        for (int k = 0; k < NN / TPB; k++) sA[t + TPB * k] = 0.0f;
        __syncthreads();

        const int epb  = (E + EB - 1) / EB;
        const int base = b * epb;
        const int cnt_ = (E - base) < epb ? (E - base) : epb;

        if ((base & 3) == 0 && (cnt_ & 3) == 0 &&
            (((unsigned long long)ei) & 15ull) == 0) {
            const int4* s4 = (const int4*)(ei) + (base >> 2);
            const int4* d4 = (const int4*)(ei + E) + (base >> 2);
            const int m4 = cnt_ >> 2;
            for (int j = t; j < m4; j += TPB) {
                int4 s = __ldg(&s4[j]);
                int4 d = __ldg(&d4[j]);
                float p0 = __ldg(&p[s.x]);
                float p1 = __ldg(&p[s.y]);
                float p2 = __ldg(&p[s.z]);
                float p3 = __ldg(&p[s.w]);
                atomicAdd(&sA[d.x], p0);   // smem atomics: no L2 involvement
                atomicAdd(&sA[d.y], p1);
                atomicAdd(&sA[d.z], p2);
                atomicAdd(&sA[d.w], p3);
            }
        } else {
            for (int e = base + t; e < base + cnt_; e += TPB) {
                int s = __ldg(&ei[e]);
                int d = __ldg(&ei[E + e]);
                atomicAdd(&sA[d], __ldg(&p[s]));
            }
        }
        __syncthreads();

        // coalesced writeout of the full partial (float4)
        float4* dst = (float4*)&g_part[b * NN];
        float4* src = (float4*)sA;
#pragma unroll
        for (int k = 0; k < NN / (TPB * 4); k++)
            dst[t + TPB * k] = src[t + TPB * k];
    } else if (b == EB) {
        // dot(x, p): deterministic double-precision tree
        double acc = 0.0;
        for (int i = t; i < n; i += TPB)
            acc += (double)x[i] * (double)p[i];
        dsh[t] = acc;
        __syncthreads();
        for (int s = TPB / 2; s > 0; s >>= 1) {
            if (t < s) dsh[t] += dsh[t + s];
            __syncthreads();
        }
        if (t == 0) g_C = (float)dsh[0];
    }
    gbar(0);

    // ---------------- Phase 2: combine partials + S + histogram -----------
    // Each block owns 64 nodes: i = b*64 + t (t < 64). Si kept in register
    // for the output phase (same i-to-thread mapping).
    float C  = g_C;
    float Si = 0.0f;
    int   myI = b * (NN / GRID) + t;
    bool  mine = (t < NN / GRID) && (myI < n);
    if (mine) {
        float A = 0.0f;
#pragma unroll 16
        for (int k = 0; k < EB; k++)
            A += g_part[k * NN + myI];         // coalesced across lanes
        float pi = __ldg(&p[myI]);
        Si = pi * logn + logf(pi + A) + C;
        g_S[myI] = Si;
        atomicAdd(&g_H[bucket_of(Si, C)], 1);  // only 8192 ops total: cheap
    }
    gbar(1);

    // ---------------- Phase 3: build (block 0): scan + counting scatter ---
    if (b == 0) {
        int* cnt = sbuf;
        // load histogram, zero it in global for next replay
        int c8[8];
        int base8 = t * 8;
#pragma unroll
        for (int k = 0; k < 8; k++) {
            c8[k] = g_H[base8 + k];
            g_H[base8 + k] = 0;
        }
        // serial exclusive prefix within thread
        int ex[8];
        int tot = 0;
#pragma unroll
        for (int k = 0; k < 8; k++) { ex[k] = tot; tot += c8[k]; }

        // warp-shuffle inclusive scan over 1024 thread totals
        int lane = t & 31, wid = t >> 5;
        int v = tot;
#pragma unroll
        for (int o = 1; o < 32; o <<= 1) {
            int u = __shfl_up_sync(0xffffffffu, v, o);
            if (lane >= o) v += u;
        }
        if (lane == 31) wsum[wid] = v;
        __syncthreads();
        if (wid == 0) {
            int w = wsum[lane];
#pragma unroll
            for (int o = 1; o < 32; o <<= 1) {
                int u = __shfl_up_sync(0xffffffffu, w, o);
                if (lane >= o) w += u;
            }
            wsum[lane] = w;
        }
        __syncthreads();
        int excl = v - tot + (wid ? wsum[wid - 1] : 0);

#pragma unroll
        for (int k = 0; k < 8; k++) {
            int pref = excl + ex[k];
            cnt[base8 + k] = pref;             // live counters
            g_P[base8 + k] = pref;             // published prefix
        }
        if (t == TPB - 1) g_P[NB] = excl + tot;
        __syncthreads();

        // counting-sort scatter (re-read S coalesced)
#pragma unroll
        for (int k = 0; k < NN / TPB; k++) {
            int i = t + TPB * k;
            float s = g_S[i];
            int bb = bucket_of(s, C);
            int pos = atomicAdd(&cnt[bb], 1);
            g_V[pos] = s;
        }
    }
    gbar(2);

    // ---------------- Phase 4: output -------------------------------------
    // out[i] = sum_j tanh(1000*(S_i - S_j) - 5). Outside band
    // [Si-0.015, Si+0.005]: exactly saturated (+1/-1) -> prefix counts.
    // Band buckets: exact per-element evaluation (incl. diagonal j=i).
    if (mine) {
        const float K   = 1000.0f;
        const float EPS = 5.0f;
        const float CUT = 10.0f;

        int loB = bucket_of(Si - 0.015f, C);
        int hiB = bucket_of(Si + 0.005f, C);

        int pLo = g_P[loB];
        int pHi = g_P[hiB + 1];
        float acc = (float)pLo - (float)(n - pHi);

        for (int idx = pLo; idx < pHi; ++idx) {
            float w   = g_V[idx];
            float arg = K * (Si - w) - EPS;
            if (arg > CUT)        acc += 1.0f;
            else if (arg < -CUT)  acc -= 1.0f;
            else                  acc += tanhf(arg);
        }
        out[myI] = acc;
    }
}

// ---------------------------------------------------------------------------
extern "C" void kernel_launch(void* const* d_in, const int* in_sizes, int n_in,
                              void* d_out, int out_size) {
    const int*   ei = (const int*)d_in[0];     // (2, E) row-major
    const float* p  = (const float*)d_in[1];   // (N,)
    const float* x  = (const float*)d_in[2];   // (N, 1)

    int E = in_sizes[0] / 2;
    int n = in_sizes[1];
    float logn = logf((float)n);

    fused<<<GRID, TPB>>>(ei, p, x, (float*)d_out, E, n, logn);
}

// round 7
// speedup vs baseline: 1.1984x; 1.1984x over previous
#include <cuda_runtime.h>
#include <math.h>
#include <stdint.h>

#define NN     8192
#define NB     8192
#define RANGEF 74000.0f
#define INV_W  ((float)NB / RANGEF)
#define GRID   148
#define TPB    1024
#define R      4              // REDG replicas (cuts same-address collisions 32 -> 8)

// Scratch (__device__ globals; zero-initialized at load; g_A4 is reset by
// block 0 every run, so every graph replay sees the same initial state).
__device__ float g_A4[R][NN];  // replicated edge segment sums
__device__ float g_S[NN];      // S per node (original order)
__device__ float g_V[NN];      // bucket-grouped copy of S
__device__ int   g_P[NB + 1];  // exclusive prefix of bucket histogram
__device__ float g_C;          // dot(x, p)

// Sense-reversing grid barrier (2 slots). Single arrival atomic, no departure
// pass. count returns to 0 and sense flips each use -> replay-safe.
__device__ int          g_count[2];
__device__ volatile int g_sense[2];

__device__ __forceinline__ void gbar(int b) {
    __syncthreads();
    if (threadIdx.x == 0) {
        int s = g_sense[b];                 // capture sense BEFORE arriving
        __threadfence();                    // publish this block's writes
        if (atomicAdd(&g_count[b], 1) == GRID - 1) {
            g_count[b] = 0;
            __threadfence();
            g_sense[b] = s ^ 1;             // release everyone
        } else {
            while (g_sense[b] == s) __nanosleep(32);
        }
        __threadfence();                    // acquire others' writes
    }
    __syncthreads();
}

// Monotone bucket map. MUST be identical at insert and query.
__device__ __forceinline__ int bucket_of(float v, float C) {
    float u = (v - C) * INV_W;
    int b = (int)u;
    if (b < 0) b = 0;
    if (b > NB - 1) b = NB - 1;
    return b;
}

// ---------------------------------------------------------------------------
__global__ void __launch_bounds__(TPB, 1)
fused(const int* __restrict__ ei, const float* __restrict__ p,
      const float* __restrict__ x, float* __restrict__ out,
      int E, int n, float logn) {

    extern __shared__ int dsm[];           // 64KB+: cnt[NB] | sV[NN] | wsum[32]
    int*   cnt  = dsm;
    float* sV   = (float*)(dsm + NB);
    int*   wsum = dsm + 2 * NB;
    double* dsh = (double*)dsm;            // aliased: dot workspace (block GRID-1)

    const int t = threadIdx.x;
    const int b = blockIdx.x;

    // ---------------- Phase A: edges (blocks 0..GRID-2) + dot (last block) --
    if (b == GRID - 1) {
        double acc = 0.0;
        for (int i = t; i < n; i += TPB)
            acc += (double)x[i] * (double)p[i];
        dsh[t] = acc;
        __syncthreads();
        for (int s = TPB / 2; s > 0; s >>= 1) {
            if (t < s) dsh[t] += dsh[t + s];
            __syncthreads();
        }
        if (t == 0) g_C = (float)dsh[0];
    } else {
        const int nthr = (GRID - 1) * TPB;
        const int tid  = b * TPB + t;
        const int rep  = t & (R - 1);
        if ((E & 3) == 0 && (((unsigned long long)ei) & 15ull) == 0) {
            const int  E4 = E >> 2;
            const int4* s4 = (const int4*)ei;
            const int4* d4 = (const int4*)(ei + E);
            for (int j = tid; j < E4; j += nthr) {
                int4 s = __ldg(&s4[j]);
                int4 d = __ldg(&d4[j]);
                float p0 = __ldg(&p[s.x]);
                float p1 = __ldg(&p[s.y]);
                float p2 = __ldg(&p[s.z]);
                float p3 = __ldg(&p[s.w]);
                atomicAdd(&g_A4[rep][d.x], p0);   // REDG, 8-way avg collisions
                atomicAdd(&g_A4[rep][d.y], p1);
                atomicAdd(&g_A4[rep][d.z], p2);
                atomicAdd(&g_A4[rep][d.w], p3);
            }
        } else {
            for (int e = tid; e < E; e += nthr) {
                int s = __ldg(&ei[e]);
                int d = __ldg(&ei[E + e]);
                atomicAdd(&g_A4[rep][d], __ldg(&p[s]));
            }
        }
    }
    gbar(0);

    // ---------------- Phase B: block 0 alone: S + hist + scan + scatter ----
    if (b == 0) {
#pragma unroll
        for (int k = 0; k < NB / TPB; k++) cnt[t + TPB * k] = 0;
        __syncthreads();

        float C = g_C;
        float sv[NN / TPB];
        int   bk[NN / TPB];
#pragma unroll
        for (int k = 0; k < NN / TPB; k++) {
            int i = t + TPB * k;
            float A = 0.0f;
#pragma unroll
            for (int r = 0; r < R; r++) {       // exact: integer-valued floats
                A += g_A4[r][i];
                g_A4[r][i] = 0.0f;              // restore invariant for replay
            }
            float pi = __ldg(&p[i]);
            float s  = pi * logn + logf(pi + A) + C;
            g_S[i] = s;
            sv[k]  = s;
            int bb = bucket_of(s, C);
            bk[k]  = bb;
            atomicAdd(&cnt[bb], 1);             // smem, spread addresses
        }
        __syncthreads();

        // Exclusive scan over 8192 bins: 8 serial per thread + shuffle scan.
        int base8 = t * 8;
        int ex[8];
        int tot = 0;
#pragma unroll
        for (int k = 0; k < 8; k++) { ex[k] = tot; tot += cnt[base8 + k]; }

        int lane = t & 31, wid = t >> 5;
        int v = tot;
#pragma unroll
        for (int o = 1; o < 32; o <<= 1) {
            int u = __shfl_up_sync(0xffffffffu, v, o);
            if (lane >= o) v += u;
        }
        if (lane == 31) wsum[wid] = v;
        __syncthreads();
        if (wid == 0) {
            int w = wsum[lane];
#pragma unroll
            for (int o = 1; o < 32; o <<= 1) {
                int u = __shfl_up_sync(0xffffffffu, w, o);
                if (lane >= o) w += u;
            }
            wsum[lane] = w;
        }
        __syncthreads();
        int excl = v - tot + (wid ? wsum[wid - 1] : 0);

#pragma unroll
        for (int k = 0; k < 8; k++) {
            int pref = excl + ex[k];
            cnt[base8 + k] = pref;              // live counters for scatter
            g_P[base8 + k] = pref;              // published prefix
        }
        if (t == TPB - 1) g_P[NB] = excl + tot;
        __syncthreads();

        // Counting-sort scatter into smem, then coalesced copy-out.
#pragma unroll
        for (int k = 0; k < NN / TPB; k++) {
            int pos = atomicAdd(&cnt[bk[k]], 1);
            sV[pos] = sv[k];
        }
        __syncthreads();
        float4* dst = (float4*)g_V;
        float4* src = (float4*)sV;
#pragma unroll
        for (int k = 0; k < NN / (TPB * 4); k++)
            dst[t + TPB * k] = src[t + TPB * k];
    }
    gbar(1);

    // ---------------- Phase C: output (blocks 0..127, 64 nodes each) -------
    // out[i] = sum_j tanh(1000*(S_i - S_j) - 5). Outside band
    // [Si-0.015, Si+0.005]: exactly saturated (+1/-1) -> prefix counts.
    // Band buckets: exact per-element evaluation (incl. diagonal j=i).
    int  myI  = b * 64 + t;
    bool mine = (b < 128) && (t < 64) && (myI < n);
    if (mine) {
        const float K   = 1000.0f;
        const float EPS = 5.0f;
        const float CUT = 10.0f;

        float C  = g_C;
        float Si = g_S[myI];

        int loB = bucket_of(Si - 0.015f, C);
        int hiB = bucket_of(Si + 0.005f, C);

        int pLo = g_P[loB];
        int pHi = g_P[hiB + 1];
        float acc = (float)pLo - (float)(n - pHi);

        for (int idx = pLo; idx < pHi; ++idx) {
            float w   = g_V[idx];
            float arg = K * (Si - w) - EPS;
            if (arg > CUT)        acc += 1.0f;
            else if (arg < -CUT)  acc -= 1.0f;
            else                  acc += tanhf(arg);
        }
        out[myI] = acc;
    }
}

// ---------------------------------------------------------------------------
extern "C" void kernel_launch(void* const* d_in, const int* in_sizes, int n_in,
                              void* d_out, int out_size) {
    const int*   ei = (const int*)d_in[0];     // (2, E) row-major
    const float* p  = (const float*)d_in[1];   // (N,)
    const float* x  = (const float*)d_in[2];   // (N, 1)

    int E = in_sizes[0] / 2;
    int n = in_sizes[1];
    float logn = logf((float)n);

    const int smem = (2 * NB + 32) * (int)sizeof(int);   // 65,664 bytes
    cudaFuncSetAttribute(fused, cudaFuncAttributeMaxDynamicSharedMemorySize, smem);
    fused<<<GRID, TPB, smem>>>(ei, p, x, (float*)d_out, E, n, logn);
}

// round 8
// speedup vs baseline: 1.2623x; 1.0533x over previous
#include <cuda_runtime.h>
#include <math.h>
#include <stdint.h>

#define NN     8192
#define NB     8192
#define RANGEF 74000.0f
#define INV_W  ((float)NB / RANGEF)
#define GRID   148
#define TPB    1024

// Scratch (__device__ globals; zero-initialized at load; g_A4 reset by block 0
// and g_arrive reset to 0 every run -> every graph replay sees clean state).
__device__ float4       g_A4[NN];   // 4 replicas per node, contiguous (one LDG.128)
__device__ float        g_C;        // dot(x, p)
__device__ volatile int g_arrive;   // arrive-only barrier counter

// Monotone bucket map. MUST be identical at insert and query.
__device__ __forceinline__ int bucket_of(float v, float C) {
    float u = (v - C) * INV_W;
    int b = (int)u;
    if (b < 0) b = 0;
    if (b > NB - 1) b = NB - 1;
    return b;
}

// ---------------------------------------------------------------------------
__global__ void __launch_bounds__(TPB, 1)
fused(const int* __restrict__ ei, const float* __restrict__ p,
      const float* __restrict__ x, float* __restrict__ out,
      int E, int n, float logn) {

    extern __shared__ int dsm[];            // cnt[NB] | sV[NN] | wsum[32]
    int*    cnt  = dsm;
    float*  sV   = (float*)(dsm + NB);
    int*    wsum = dsm + 2 * NB;
    double* dsh  = (double*)dsm;            // alias: dot workspace (block GRID-1)

    const int t = threadIdx.x;
    const int b = blockIdx.x;

    // ---------------- Phase A: edges (blocks 0..GRID-2) + dot (last) -------
    if (b == GRID - 1) {
        double acc = 0.0;
        for (int i = t; i < n; i += TPB)
            acc += (double)x[i] * (double)p[i];
        dsh[t] = acc;
        __syncthreads();
        for (int s = TPB / 2; s > 0; s >>= 1) {
            if (t < s) dsh[t] += dsh[t + s];
            __syncthreads();
        }
        if (t == 0) g_C = (float)dsh[0];
    } else {
        const int nthr = (GRID - 1) * TPB;
        const int tid  = b * TPB + t;
        const int rep  = t & 3;
        float* A = (float*)g_A4;            // node i replicas at A[4*i + rep]
        if ((E & 3) == 0 && (((unsigned long long)ei) & 15ull) == 0) {
            const int  E4 = E >> 2;
            const int4* s4 = (const int4*)ei;
            const int4* d4 = (const int4*)(ei + E);
            for (int j = tid; j < E4; j += nthr) {
                int4 s = __ldg(&s4[j]);
                int4 d = __ldg(&d4[j]);
                float p0 = __ldg(&p[s.x]);
                float p1 = __ldg(&p[s.y]);
                float p2 = __ldg(&p[s.z]);
                float p3 = __ldg(&p[s.w]);
                atomicAdd(&A[4 * d.x + rep], p0);   // REDG, fire-and-forget
                atomicAdd(&A[4 * d.y + rep], p1);
                atomicAdd(&A[4 * d.z + rep], p2);
                atomicAdd(&A[4 * d.w + rep], p3);
            }
        } else {
            for (int e = tid; e < E; e += nthr) {
                int s = __ldg(&ei[e]);
                int d = __ldg(&ei[E + e]);
                atomicAdd(&A[4 * d + rep], __ldg(&p[s]));
            }
        }
    }

    // ---------------- Arrive-only barrier ----------------------------------
    __threadfence();                        // publish REDGs / g_C
    __syncthreads();
    if (b != 0) {
        if (t == 0) atomicAdd((int*)&g_arrive, 1);
        return;                             // blocks 1..GRID-1 are DONE
    }
    if (t == 0) {
        while (g_arrive != GRID - 1) __nanosleep(32);
        g_arrive = 0;                       // reset for next graph replay
        __threadfence();
    }
    __syncthreads();

    // ================= Block 0 serial tail (all in smem/regs) ==============
    // Zero histogram.
#pragma unroll
    for (int k = 0; k < NB / TPB; k++) cnt[t + TPB * k] = 0;
    __syncthreads();

    const float C = *(volatile float*)&g_C;

    // S + histogram. Node mapping i = t + 1024k reused for output below.
    float sv[NN / TPB];
    int   bk[NN / TPB];
    const float4 z4 = make_float4(0.f, 0.f, 0.f, 0.f);
#pragma unroll
    for (int k = 0; k < NN / TPB; k++) {
        int i = t + TPB * k;
        float4 a = __ldcg(&g_A4[i]);        // L2 (bypass L1: written via REDG)
        g_A4[i] = z4;                       // restore invariant for replay
        float A  = (a.x + a.y) + (a.z + a.w);  // exact: integer-valued floats
        float pi = __ldg(&p[i]);
        float s  = pi * logn + logf(pi + A) + C;
        sv[k] = s;
        int bb = bucket_of(s, C);
        bk[k] = bb;
        atomicAdd(&cnt[bb], 1);             // smem, spread addresses
    }
    __syncthreads();

    // Exclusive scan over 8192 bins: 8 serial per thread + shuffle scan.
    int base8 = t * 8;
    int ex[8];
    int tot = 0;
#pragma unroll
    for (int k = 0; k < 8; k++) { ex[k] = tot; tot += cnt[base8 + k]; }

    int lane = t & 31, wid = t >> 5;
    int v = tot;
#pragma unroll
    for (int o = 1; o < 32; o <<= 1) {
        int u = __shfl_up_sync(0xffffffffu, v, o);
        if (lane >= o) v += u;
    }
    if (lane == 31) wsum[wid] = v;
    __syncthreads();
    if (wid == 0) {
        int w = wsum[lane];
#pragma unroll
        for (int o = 1; o < 32; o <<= 1) {
            int u = __shfl_up_sync(0xffffffffu, w, o);
            if (lane >= o) w += u;
        }
        wsum[lane] = w;
    }
    __syncthreads();
    int excl = v - tot + (wid ? wsum[wid - 1] : 0);

#pragma unroll
    for (int k = 0; k < 8; k++)
        cnt[base8 + k] = excl + ex[k];      // live counters (= bucket starts)
    __syncthreads();

    // Counting-sort scatter into smem. Afterwards cnt[b] == P[b+1] (ends).
#pragma unroll
    for (int k = 0; k < NN / TPB; k++) {
        int pos = atomicAdd(&cnt[bk[k]], 1);
        sV[pos] = sv[k];
    }
    __syncthreads();

    // Output: out[i] = sum_j tanh(1000*(S_i - S_j) - 5). Outside band
    // [Si-0.015, Si+0.005]: exactly saturated (+1/-1) -> prefix counts
    // (pLo = P[loB] = cnt[loB-1], pHi = P[hiB+1] = cnt[hiB]).
    // Band buckets: exact per-element evaluation (incl. diagonal j=i).
    const float K   = 1000.0f;
    const float EPS = 5.0f;
    const float CUT = 10.0f;
#pragma unroll
    for (int k = 0; k < NN / TPB; k++) {
        int i = t + TPB * k;
        if (i >= n) break;
        float Si = sv[k];

        int loB = bucket_of(Si - 0.015f, C);
        int hiB = bucket_of(Si + 0.005f, C);

        int pLo = (loB > 0) ? cnt[loB - 1] : 0;
        int pHi = cnt[hiB];
        float acc = (float)pLo - (float)(n - pHi);

        for (int idx = pLo; idx < pHi; ++idx) {
            float w   = sV[idx];
            float arg = K * (Si - w) - EPS;
            if (arg > CUT)        acc += 1.0f;
            else if (arg < -CUT)  acc -= 1.0f;
            else                  acc += tanhf(arg);
        }
        out[i] = acc;                       // coalesced
    }
}

// ---------------------------------------------------------------------------
extern "C" void kernel_launch(void* const* d_in, const int* in_sizes, int n_in,
                              void* d_out, int out_size) {
    const int*   ei = (const int*)d_in[0];     // (2, E) row-major
    const float* p  = (const float*)d_in[1];   // (N,)
    const float* x  = (const float*)d_in[2];   // (N, 1)

    int E = in_sizes[0] / 2;
    int n = in_sizes[1];
    float logn = logf((float)n);

    const int smem = (2 * NB + 32) * (int)sizeof(int);   // 65,664 bytes
    cudaFuncSetAttribute(fused, cudaFuncAttributeMaxDynamicSharedMemorySize, smem);
    fused<<<GRID, TPB, smem>>>(ei, p, x, (float*)d_out, E, n, logn);
}